// round 9
// baseline (speedup 1.0000x reference)
#include <cuda_runtime.h>
#include <cuda_fp16.h>
#include <math.h>

// Problem dims (fixed)
#define B_      8
#define H_      32
#define TQ_     8
#define KV_     4096
#define D_      128

// Split-KV config
#define NSPLIT_ 8
#define KVS_    (KV_ / NSPLIT_)   // 512 rows per split
#define RPI_    64                // rows per iteration (two 32-row halves)
#define NITER_  (KVS_ / RPI_)     // 8
#define NPART_  (B_ * H_ * NSPLIT_) // 2048

typedef unsigned long long u64;

// Scratch for split partials (device globals: allocation-free)
__device__ float g_po[NPART_ * TQ_ * D_];  // unnormalized partial outputs
__device__ float g_pm[NPART_ * TQ_];       // running max per (part, query)
__device__ float g_pl[NPART_ * TQ_];       // running sum-exp per (part, query)

// ---- packed f32x2 helpers (Blackwell) ----
__device__ __forceinline__ u64 fma2(u64 a, u64 b, u64 c) {
    u64 d; asm("fma.rn.f32x2 %0, %1, %2, %3;" : "=l"(d) : "l"(a), "l"(b), "l"(c));
    return d;
}
__device__ __forceinline__ u64 mul2(u64 a, u64 b) {
    u64 d; asm("mul.rn.f32x2 %0, %1, %2;" : "=l"(d) : "l"(a), "l"(b));
    return d;
}
__device__ __forceinline__ u64 pack2(float lo, float hi) {
    u64 d; asm("mov.b64 %0, {%1, %2};" : "=l"(d) : "f"(lo), "f"(hi));
    return d;
}
__device__ __forceinline__ float2 unpack2(u64 a) {
    float lo, hi; asm("mov.b64 {%0, %1}, %2;" : "=f"(lo), "=f"(hi) : "l"(a));
    return make_float2(lo, hi);
}
// fp16 round-trip of two floats, result packed as f32x2
__device__ __forceinline__ u64 h16rt2(float a, float b) {
    __half2 h = __floats2half2_rn(a, b);
    float2 f = __half22float2(h);
    return pack2(f.x, f.y);
}

__device__ __forceinline__ float tern(float x, float th) {
    // ternary {-1,0,+1}: strictly outside [-th, th]
    return (fabsf(x) > th) ? copysignf(1.0f, x) : 0.0f;
}

// scalar reduce-scatter of 8 query-dots over 8 d-octant lanes (3 rounds)
__device__ __forceinline__ float reduce_scatter8(const float* s, bool b2, bool b1, bool b0) {
    const float r0 = __shfl_xor_sync(0xffffffffu, b2 ? s[0] : s[4], 4);
    const float r1 = __shfl_xor_sync(0xffffffffu, b2 ? s[1] : s[5], 4);
    const float r2 = __shfl_xor_sync(0xffffffffu, b2 ? s[2] : s[6], 4);
    const float r3 = __shfl_xor_sync(0xffffffffu, b2 ? s[3] : s[7], 4);
    const float A0 = (b2 ? s[4] : s[0]) + r0;
    const float A1 = (b2 ? s[5] : s[1]) + r1;
    const float A2 = (b2 ? s[6] : s[2]) + r2;
    const float A3 = (b2 ? s[7] : s[3]) + r3;
    const float r4 = __shfl_xor_sync(0xffffffffu, b1 ? A0 : A2, 2);
    const float r5 = __shfl_xor_sync(0xffffffffu, b1 ? A1 : A3, 2);
    const float C0 = (b1 ? A2 : A0) + r4;
    const float C1 = (b1 ? A3 : A1) + r5;
    const float r6 = __shfl_xor_sync(0xffffffffu, b0 ? C0 : C1, 1);
    return (b0 ? C1 : C0) + r6;
}

__global__ __launch_bounds__(256, 2)
void attn_split_kernel(const float* __restrict__ q,
                       const float* __restrict__ k,
                       const float* __restrict__ v,
                       const float* __restrict__ logth)
{
    __shared__ __align__(16) float q_sm[TQ_ * D_];    // q * (scale*thresh)
    __shared__ __align__(16) float p_w[8][TQ_][8];    // probs [w][j][rrA(0..3),rrB(4..7)]
    __shared__ float m_sm[8][TQ_];                    // epilogue: per-warp m
    __shared__ float l_sm[8][TQ_];                    // epilogue: per-warp l
    __shared__ __align__(16) float red_sm[8][D_];     // epilogue cross-warp reduce

    const int bid   = blockIdx.x;
    const int bh    = bid >> 3;              // (b*H + h)
    const int split = bid & (NSPLIT_ - 1);
    const int h     = bh & (H_ - 1);
    const int t     = threadIdx.x;
    const int w     = t >> 5;                // warp id
    const int lane  = t & 31;
    const int ar    = t >> 3;                // dot row within half (0..31): 4w + rr
    const int adq   = t & 7;                 // d-octant AND assigned query
    const int rr    = lane >> 3;             // row-within-warp (0..3)

    // softplus (numerically stable, matches jax.nn.softplus)
    const float lt = logth[h];
    const float th = fmaxf(lt, 0.0f) + log1pf(expf(-fabsf(lt)));
    const float qmul = th * 0.08838834764831845f;   // thresh / sqrt(128)

    const float* qb = q + (size_t)bh * (TQ_ * D_);
    const float* kb = k + (size_t)bh * (KV_ * D_) + (size_t)split * (KVS_ * D_);
    const float* vb = v + (size_t)bh * (KV_ * D_) + (size_t)split * (KVS_ * D_);

    // load q scaled by thresh*scale (so k dequant is just {-1,0,1})
    for (int i = t; i < TQ_ * D_; i += 256) q_sm[i] = qb[i] * qmul;
    __syncthreads();

    // packed output accumulators (this warp's rows only; merged in epilogue)
    u64 o01[TQ_], o23[TQ_];
#pragma unroll
    for (int j = 0; j < TQ_; j++) { o01[j] = 0ULL; o23[j] = 0ULL; }
    float m_run = -INFINITY, l_run = 0.0f;

    const bool b2 = (adq & 4) != 0;
    const bool b1 = (adq & 2) != 0;
    const bool b0 = (adq & 1) != 0;

    // K registers for both 32-row halves of the 64-row iteration
    float4 kkA[4], kkB[4];
    {
        const float* kpA = kb + ar * D_ + adq * 4;
        const float* kpB = kb + (32 + ar) * D_ + adq * 4;
#pragma unroll
        for (int i = 0; i < 4; i++) kkA[i] = *(const float4*)(kpA + i * 32);
#pragma unroll
        for (int i = 0; i < 4; i++) kkB[i] = *(const float4*)(kpB + i * 32);
    }

    const int brow = w << 2;        // this warp's rows within a half: 4w..4w+3
    const int bd   = lane << 2;     // output column base

#pragma unroll 1
    for (int it = 0; it < NITER_; it++) {
        // ---- ternary dequant for both halves (kk dead after this) ----
        u64 EA0[4], EA1[4], EB0[4], EB1[4];
#pragma unroll
        for (int i = 0; i < 4; i++) {
            EA0[i] = pack2(tern(kkA[i].x, th), tern(kkA[i].y, th));
            EA1[i] = pack2(tern(kkA[i].z, th), tern(kkA[i].w, th));
            EB0[i] = pack2(tern(kkB[i].x, th), tern(kkB[i].y, th));
            EB1[i] = pack2(tern(kkB[i].z, th), tern(kkB[i].w, th));
        }

        // ---- dot: each q LDS.128 feeds 4 fma2 (both row-halves) ----
        float sA[TQ_], sB[TQ_];
#pragma unroll
        for (int j = 0; j < TQ_; j++) {
            u64 accA = 0ULL, accB = 0ULL;
            const float* qp = q_sm + adq * 4 + j * D_;
#pragma unroll
            for (int i = 0; i < 4; i++) {
                const ulonglong2 q2 = *(const ulonglong2*)(qp + i * 32);
                accA = fma2(q2.x, EA0[i], accA);
                accA = fma2(q2.y, EA1[i], accA);
                accB = fma2(q2.x, EB0[i], accB);
                accB = fma2(q2.y, EB1[i], accB);
            }
            const float2 hA = unpack2(accA);
            const float2 hB = unpack2(accB);
            sA[j] = hA.x + hA.y;
            sB[j] = hB.x + hB.y;
        }

        // ---- V loads early (covered by reduce-scatter + softmax) ----
        float4 vvA[4], vvB[4];
        {
            const float* vpA = vb + (size_t)(it * RPI_ + brow) * D_ + bd;
            const float* vpB = vpA + 32 * D_;
#pragma unroll
            for (int i2 = 0; i2 < 4; i2++) vvA[i2] = *(const float4*)(vpA + i2 * D_);
#pragma unroll
            for (int i2 = 0; i2 < 4; i2++) vvB[i2] = *(const float4*)(vpB + i2 * D_);
        }

        // ---- reduce-scatter both halves: lane adq gets query adq ----
        const float ownA = reduce_scatter8(sA, b2, b1, b0);
        const float ownB = reduce_scatter8(sB, b2, b1, b0);

        // ---- one online softmax update per 64 rows (8 rows per warp) ----
        float alpha;
        {
            float mt = fmaxf(ownA, ownB);
            mt = fmaxf(mt, __shfl_xor_sync(0xffffffffu, mt, 8));
            mt = fmaxf(mt, __shfl_xor_sync(0xffffffffu, mt, 16));
            const float m_new = fmaxf(m_run, mt);
            alpha = __expf(m_run - m_new);  // 0 on first iteration
            const float pA = __expf(ownA - m_new);
            const float pB = __expf(ownB - m_new);
            float ps = pA + pB;
            ps += __shfl_xor_sync(0xffffffffu, ps, 8);
            ps += __shfl_xor_sync(0xffffffffu, ps, 16);
            l_run = l_run * alpha + ps;
            m_run = m_new;
            p_w[w][adq][rr]     = pA;
            p_w[w][adq][4 + rr] = pB;
        }
        __syncwarp();

        // ---- prefetch next iteration's K (covered by phase B + next E/dot) ----
        if (it + 1 < NITER_) {
            const float* kpA = kb + (size_t)((it + 1) * RPI_ + ar) * D_ + adq * 4;
            const float* kpB = kpA + 32 * D_;
#pragma unroll
            for (int i = 0; i < 4; i++) kkA[i] = *(const float4*)(kpA + i * 32);
#pragma unroll
            for (int i = 0; i < 4; i++) kkB[i] = *(const float4*)(kpB + i * 32);
        }

        // ---- rescale (skipped when warp-uniformly alpha == 1) ----
        if (!__all_sync(0xffffffffu, alpha == 1.0f)) {
#pragma unroll
            for (int j = 0; j < TQ_; j++) {
                const float a = __shfl_sync(0xffffffffu, alpha, j, 8);
                const u64 A2v = pack2(a, a);
                o01[j] = mul2(o01[j], A2v);
                o23[j] = mul2(o23[j], A2v);
            }
        }

        // ---- phase B half A ----
        {
            u64 V01[4], V23[4];
#pragma unroll
            for (int i2 = 0; i2 < 4; i2++) {
                V01[i2] = h16rt2(vvA[i2].x, vvA[i2].y);   // exact fp16 round-trip
                V23[i2] = h16rt2(vvA[i2].z, vvA[i2].w);
            }
#pragma unroll
            for (int j = 0; j < TQ_; j++) {
                const float4 p4 = *(const float4*)&p_w[w][j][0];
                u64 x01 = o01[j], x23 = o23[j];
                u64 P;
                P = pack2(p4.x, p4.x); x01 = fma2(P, V01[0], x01); x23 = fma2(P, V23[0], x23);
                P = pack2(p4.y, p4.y); x01 = fma2(P, V01[1], x01); x23 = fma2(P, V23[1], x23);
                P = pack2(p4.z, p4.z); x01 = fma2(P, V01[2], x01); x23 = fma2(P, V23[2], x23);
                P = pack2(p4.w, p4.w); x01 = fma2(P, V01[3], x01); x23 = fma2(P, V23[3], x23);
                o01[j] = x01; o23[j] = x23;
            }
        }
        // ---- phase B half B ----
        {
            u64 V01[4], V23[4];
#pragma unroll
            for (int i2 = 0; i2 < 4; i2++) {
                V01[i2] = h16rt2(vvB[i2].x, vvB[i2].y);
                V23[i2] = h16rt2(vvB[i2].z, vvB[i2].w);
            }
#pragma unroll
            for (int j = 0; j < TQ_; j++) {
                const float4 p4 = *(const float4*)&p_w[w][j][4];
                u64 x01 = o01[j], x23 = o23[j];
                u64 P;
                P = pack2(p4.x, p4.x); x01 = fma2(P, V01[0], x01); x23 = fma2(P, V23[0], x23);
                P = pack2(p4.y, p4.y); x01 = fma2(P, V01[1], x01); x23 = fma2(P, V23[1], x23);
                P = pack2(p4.z, p4.z); x01 = fma2(P, V01[2], x01); x23 = fma2(P, V23[2], x23);
                P = pack2(p4.w, p4.w); x01 = fma2(P, V01[3], x01); x23 = fma2(P, V23[3], x23);
                o01[j] = x01; o23[j] = x23;
            }
        }
        __syncwarp();   // protect p_w before next iteration's overwrite
    }

    // ---- epilogue: merge 8 per-warp (m,l,O) by log-sum-exp, write partial ----
    if (rr == 0) { m_sm[w][adq] = m_run; l_sm[w][adq] = l_run; }
    __syncthreads();

    float sc[TQ_];
#pragma unroll
    for (int j = 0; j < TQ_; j++) {
        float M = m_sm[0][j];
#pragma unroll
        for (int w2 = 1; w2 < 8; w2++) M = fmaxf(M, m_sm[w2][j]);
        sc[j] = __expf(m_sm[w][j] - M);   // this warp's rescale to CTA max
    }
    {
        const size_t pbase = (size_t)bid * (TQ_ * D_);
#pragma unroll 1
        for (int j = 0; j < TQ_; j++) {
            __syncthreads();   // previous iteration's reads done
            const u64 S2 = pack2(sc[j], sc[j]);
            const float2 a01 = unpack2(mul2(o01[j], S2));
            const float2 a23 = unpack2(mul2(o23[j], S2));
            *(float4*)&red_sm[w][bd] = make_float4(a01.x, a01.y, a23.x, a23.y);
            __syncthreads();
            if (t < D_) {
                float acc = red_sm[0][t];
#pragma unroll
                for (int w2 = 1; w2 < 8; w2++) acc += red_sm[w2][t];
                g_po[pbase + j * D_ + t] = acc;
            }
        }
        if (t < TQ_) {   // thread t == query j
            float M = m_sm[0][t];
#pragma unroll
            for (int w2 = 1; w2 < 8; w2++) M = fmaxf(M, m_sm[w2][t]);
            float L = 0.0f;
#pragma unroll
            for (int w2 = 0; w2 < 8; w2++)
                L = fmaf(__expf(m_sm[w2][t] - M), l_sm[w2][t], L);
            g_pm[bid * TQ_ + t] = M;
            g_pl[bid * TQ_ + t] = L;
        }
    }
}

__global__ __launch_bounds__(256)
void combine_kernel(float* __restrict__ out)
{
    const int bh = blockIdx.x;          // 0..255
    const int t  = threadIdx.x;
    const int j  = t >> 5;              // query
    const int d4 = (t & 31) << 2;       // column base

    float m[NSPLIT_];
    float M = -INFINITY;
#pragma unroll
    for (int i = 0; i < NSPLIT_; i++) {
        m[i] = g_pm[(bh * NSPLIT_ + i) * TQ_ + j];
        M = fmaxf(M, m[i]);
    }
    float W = 0.0f;
    float ax = 0.f, ay = 0.f, az = 0.f, aw = 0.f;
#pragma unroll
    for (int i = 0; i < NSPLIT_; i++) {
        const float wgt = __expf(m[i] - M);
        W = fmaf(wgt, g_pl[(bh * NSPLIT_ + i) * TQ_ + j], W);
        const float4 oi = *(const float4*)&g_po[((size_t)(bh * NSPLIT_ + i) * TQ_ + j) * D_ + d4];
        ax = fmaf(wgt, oi.x, ax);
        ay = fmaf(wgt, oi.y, ay);
        az = fmaf(wgt, oi.z, az);
        aw = fmaf(wgt, oi.w, aw);
    }
    const float inv = 1.0f / W;
    float4 r = make_float4(ax * inv, ay * inv, az * inv, aw * inv);
    *(float4*)&out[(size_t)bh * (TQ_ * D_) + j * D_ + d4] = r;
}

// diagnostic: pads launch count so ncu (-s 5 -c 1, observed +2 offset)
// lands on attn_split_kernel (profiled slot = our 4th launch)
__global__ void nop_kernel() {}

extern "C" void kernel_launch(void* const* d_in, const int* in_sizes, int n_in,
                              void* d_out, int out_size)
{
    const float* q    = (const float*)d_in[0];
    const float* k    = (const float*)d_in[1];
    const float* v    = (const float*)d_in[2];
    const float* logt = (const float*)d_in[3];
    float* out = (float*)d_out;

    nop_kernel<<<1, 32>>>();
    nop_kernel<<<1, 32>>>();
    nop_kernel<<<1, 32>>>();
    attn_split_kernel<<<NPART_, 256>>>(q, k, v, logt);
    combine_kernel<<<B_ * H_, 256>>>(out);
}

// round 10
// speedup vs baseline: 1.0094x; 1.0094x over previous
#include <cuda_runtime.h>
#include <cuda_fp16.h>
#include <math.h>

// Problem dims (fixed)
#define B_      8
#define H_      32
#define TQ_     8
#define KV_     4096
#define D_      128

// Split-KV config
#define NSPLIT_ 8
#define KVS_    (KV_ / NSPLIT_)   // 512 rows per split
#define RPI_    64                // rows per iteration (two 32-row halves)
#define NITER_  (KVS_ / RPI_)     // 8
#define NPART_  (B_ * H_ * NSPLIT_) // 2048

typedef unsigned long long u64;

// Scratch for split partials (device globals: allocation-free)
__device__ float g_po[NPART_ * TQ_ * D_];  // unnormalized partial outputs
__device__ float g_pm[NPART_ * TQ_];       // running max per (part, query)
__device__ float g_pl[NPART_ * TQ_];       // running sum-exp per (part, query)

// ---- packed f32x2 helpers (Blackwell) ----
__device__ __forceinline__ u64 fma2(u64 a, u64 b, u64 c) {
    u64 d; asm("fma.rn.f32x2 %0, %1, %2, %3;" : "=l"(d) : "l"(a), "l"(b), "l"(c));
    return d;
}
__device__ __forceinline__ u64 mul2(u64 a, u64 b) {
    u64 d; asm("mul.rn.f32x2 %0, %1, %2;" : "=l"(d) : "l"(a), "l"(b));
    return d;
}
__device__ __forceinline__ u64 pack2(float lo, float hi) {
    u64 d; asm("mov.b64 %0, {%1, %2};" : "=l"(d) : "f"(lo), "f"(hi));
    return d;
}
__device__ __forceinline__ float2 unpack2(u64 a) {
    float lo, hi; asm("mov.b64 {%0, %1}, %2;" : "=f"(lo), "=f"(hi) : "l"(a));
    return make_float2(lo, hi);
}
// fp16 round-trip of two floats, result packed as f32x2
__device__ __forceinline__ u64 h16rt2(float a, float b) {
    __half2 h = __floats2half2_rn(a, b);
    float2 f = __half22float2(h);
    return pack2(f.x, f.y);
}

__device__ __forceinline__ float tern(float x, float th) {
    // ternary {-1,0,+1}: strictly outside [-th, th]
    return (fabsf(x) > th) ? copysignf(1.0f, x) : 0.0f;
}

// scalar reduce-scatter of 8 query-dots over 8 d-octant lanes (3 rounds)
__device__ __forceinline__ float reduce_scatter8(const float* s, bool b2, bool b1, bool b0) {
    const float r0 = __shfl_xor_sync(0xffffffffu, b2 ? s[0] : s[4], 4);
    const float r1 = __shfl_xor_sync(0xffffffffu, b2 ? s[1] : s[5], 4);
    const float r2 = __shfl_xor_sync(0xffffffffu, b2 ? s[2] : s[6], 4);
    const float r3 = __shfl_xor_sync(0xffffffffu, b2 ? s[3] : s[7], 4);
    const float A0 = (b2 ? s[4] : s[0]) + r0;
    const float A1 = (b2 ? s[5] : s[1]) + r1;
    const float A2 = (b2 ? s[6] : s[2]) + r2;
    const float A3 = (b2 ? s[7] : s[3]) + r3;
    const float r4 = __shfl_xor_sync(0xffffffffu, b1 ? A0 : A2, 2);
    const float r5 = __shfl_xor_sync(0xffffffffu, b1 ? A1 : A3, 2);
    const float C0 = (b1 ? A2 : A0) + r4;
    const float C1 = (b1 ? A3 : A1) + r5;
    const float r6 = __shfl_xor_sync(0xffffffffu, b0 ? C0 : C1, 1);
    return (b0 ? C1 : C0) + r6;
}

__global__ __launch_bounds__(256, 2)
void attn_split_kernel(const float* __restrict__ q,
                       const float* __restrict__ k,
                       const float* __restrict__ v,
                       const float* __restrict__ logth)
{
    __shared__ __align__(16) float q_sm[TQ_ * D_];    // q * (scale*thresh)
    __shared__ __align__(16) float p_w[8][TQ_][8];    // probs [w][j][rrA(0..3),rrB(4..7)]
    __shared__ float m_sm[8][TQ_];                    // epilogue: per-warp m
    __shared__ float l_sm[8][TQ_];                    // epilogue: per-warp l
    __shared__ __align__(16) float red_sm[8][D_];     // epilogue cross-warp reduce

    const int bid   = blockIdx.x;
    const int bh    = bid >> 3;              // (b*H + h)
    const int split = bid & (NSPLIT_ - 1);
    const int h     = bh & (H_ - 1);
    const int t     = threadIdx.x;
    const int w     = t >> 5;                // warp id
    const int lane  = t & 31;
    const int ar    = t >> 3;                // dot row within half (0..31): 4w + rr
    const int adq   = t & 7;                 // d-octant AND assigned query
    const int rr    = lane >> 3;             // row-within-warp (0..3)

    // softplus (numerically stable, matches jax.nn.softplus)
    const float lt = logth[h];
    const float th = fmaxf(lt, 0.0f) + log1pf(expf(-fabsf(lt)));
    const float qmul = th * 0.08838834764831845f;   // thresh / sqrt(128)

    const float* qb = q + (size_t)bh * (TQ_ * D_);
    const float* kb = k + (size_t)bh * (KV_ * D_) + (size_t)split * (KVS_ * D_);
    const float* vb = v + (size_t)bh * (KV_ * D_) + (size_t)split * (KVS_ * D_);

    // load q scaled by thresh*scale (so k dequant is just {-1,0,1})
    for (int i = t; i < TQ_ * D_; i += 256) q_sm[i] = qb[i] * qmul;
    __syncthreads();

    // packed output accumulators (this warp's rows only; merged in epilogue)
    u64 o01[TQ_], o23[TQ_];
#pragma unroll
    for (int j = 0; j < TQ_; j++) { o01[j] = 0ULL; o23[j] = 0ULL; }
    float m_run = -INFINITY, l_run = 0.0f;

    const bool b2 = (adq & 4) != 0;
    const bool b1 = (adq & 2) != 0;
    const bool b0 = (adq & 1) != 0;

    // K registers for both 32-row halves of the 64-row iteration
    float4 kkA[4], kkB[4];
    {
        const float* kpA = kb + ar * D_ + adq * 4;
        const float* kpB = kb + (32 + ar) * D_ + adq * 4;
#pragma unroll
        for (int i = 0; i < 4; i++) kkA[i] = *(const float4*)(kpA + i * 32);
#pragma unroll
        for (int i = 0; i < 4; i++) kkB[i] = *(const float4*)(kpB + i * 32);
    }

    const int brow = w << 2;        // this warp's rows within a half: 4w..4w+3
    const int bd   = lane << 2;     // output column base

#pragma unroll 1
    for (int it = 0; it < NITER_; it++) {
        // ---- ternary dequant for both halves (kk dead after this) ----
        u64 EA0[4], EA1[4], EB0[4], EB1[4];
#pragma unroll
        for (int i = 0; i < 4; i++) {
            EA0[i] = pack2(tern(kkA[i].x, th), tern(kkA[i].y, th));
            EA1[i] = pack2(tern(kkA[i].z, th), tern(kkA[i].w, th));
            EB0[i] = pack2(tern(kkB[i].x, th), tern(kkB[i].y, th));
            EB1[i] = pack2(tern(kkB[i].z, th), tern(kkB[i].w, th));
        }

        // ---- dot: each q LDS.128 feeds 4 fma2 (both row-halves) ----
        float sA[TQ_], sB[TQ_];
#pragma unroll
        for (int j = 0; j < TQ_; j++) {
            u64 accA = 0ULL, accB = 0ULL;
            const float* qp = q_sm + adq * 4 + j * D_;
#pragma unroll
            for (int i = 0; i < 4; i++) {
                const ulonglong2 q2 = *(const ulonglong2*)(qp + i * 32);
                accA = fma2(q2.x, EA0[i], accA);
                accA = fma2(q2.y, EA1[i], accA);
                accB = fma2(q2.x, EB0[i], accB);
                accB = fma2(q2.y, EB1[i], accB);
            }
            const float2 hA = unpack2(accA);
            const float2 hB = unpack2(accB);
            sA[j] = hA.x + hA.y;
            sB[j] = hB.x + hB.y;
        }
        // E arrays dead here; s(16) + o(32) live.

        // ---- V loads (covered by reduce-scatter + softmax) ----
        float4 vvA[4], vvB[4];
        {
            const float* vpA = vb + (size_t)(it * RPI_ + brow) * D_ + bd;
            const float* vpB = vpA + 32 * D_;
#pragma unroll
            for (int i2 = 0; i2 < 4; i2++) vvA[i2] = *(const float4*)(vpA + i2 * D_);
#pragma unroll
            for (int i2 = 0; i2 < 4; i2++) vvB[i2] = *(const float4*)(vpB + i2 * D_);
        }

        // ---- reduce-scatter both halves: lane adq gets query adq ----
        const float ownA = reduce_scatter8(sA, b2, b1, b0);
        const float ownB = reduce_scatter8(sB, b2, b1, b0);

        // ---- one online softmax update per 64 rows (8 rows per warp) ----
        float alpha;
        {
            float mt = fmaxf(ownA, ownB);
            mt = fmaxf(mt, __shfl_xor_sync(0xffffffffu, mt, 8));
            mt = fmaxf(mt, __shfl_xor_sync(0xffffffffu, mt, 16));
            const float m_new = fmaxf(m_run, mt);
            alpha = __expf(m_run - m_new);  // 0 on first iteration
            const float pA = __expf(ownA - m_new);
            const float pB = __expf(ownB - m_new);
            float ps = pA + pB;
            ps += __shfl_xor_sync(0xffffffffu, ps, 8);
            ps += __shfl_xor_sync(0xffffffffu, ps, 16);
            l_run = l_run * alpha + ps;
            m_run = m_new;
            p_w[w][adq][rr]     = pA;
            p_w[w][adq][4 + rr] = pB;
        }
        __syncwarp();

        // ---- rescale (skipped when warp-uniformly alpha == 1) ----
        if (!__all_sync(0xffffffffu, alpha == 1.0f)) {
#pragma unroll
            for (int j = 0; j < TQ_; j++) {
                const float a = __shfl_sync(0xffffffffu, alpha, j, 8);
                const u64 A2v = pack2(a, a);
                o01[j] = mul2(o01[j], A2v);
                o23[j] = mul2(o23[j], A2v);
            }
        }

        // ---- phase B half A (vvA dies into V01/V23 immediately) ----
        {
            u64 V01[4], V23[4];
#pragma unroll
            for (int i2 = 0; i2 < 4; i2++) {
                V01[i2] = h16rt2(vvA[i2].x, vvA[i2].y);   // exact fp16 round-trip
                V23[i2] = h16rt2(vvA[i2].z, vvA[i2].w);
            }
#pragma unroll
            for (int j = 0; j < TQ_; j++) {
                const float4 p4 = *(const float4*)&p_w[w][j][0];
                u64 x01 = o01[j], x23 = o23[j];
                u64 P;
                P = pack2(p4.x, p4.x); x01 = fma2(P, V01[0], x01); x23 = fma2(P, V23[0], x23);
                P = pack2(p4.y, p4.y); x01 = fma2(P, V01[1], x01); x23 = fma2(P, V23[1], x23);
                P = pack2(p4.z, p4.z); x01 = fma2(P, V01[2], x01); x23 = fma2(P, V23[2], x23);
                P = pack2(p4.w, p4.w); x01 = fma2(P, V01[3], x01); x23 = fma2(P, V23[3], x23);
                o01[j] = x01; o23[j] = x23;
            }
        }

        // ---- prefetch next iteration's K (vvA/V_A dead; kk regs free) ----
        if (it + 1 < NITER_) {
            const float* kpA = kb + (size_t)((it + 1) * RPI_ + ar) * D_ + adq * 4;
            const float* kpB = kpA + 32 * D_;
#pragma unroll
            for (int i = 0; i < 4; i++) kkA[i] = *(const float4*)(kpA + i * 32);
#pragma unroll
            for (int i = 0; i < 4; i++) kkB[i] = *(const float4*)(kpB + i * 32);
        }

        // ---- phase B half B ----
        {
            u64 V01[4], V23[4];
#pragma unroll
            for (int i2 = 0; i2 < 4; i2++) {
                V01[i2] = h16rt2(vvB[i2].x, vvB[i2].y);
                V23[i2] = h16rt2(vvB[i2].z, vvB[i2].w);
            }
#pragma unroll
            for (int j = 0; j < TQ_; j++) {
                const float4 p4 = *(const float4*)&p_w[w][j][4];
                u64 x01 = o01[j], x23 = o23[j];
                u64 P;
                P = pack2(p4.x, p4.x); x01 = fma2(P, V01[0], x01); x23 = fma2(P, V23[0], x23);
                P = pack2(p4.y, p4.y); x01 = fma2(P, V01[1], x01); x23 = fma2(P, V23[1], x23);
                P = pack2(p4.z, p4.z); x01 = fma2(P, V01[2], x01); x23 = fma2(P, V23[2], x23);
                P = pack2(p4.w, p4.w); x01 = fma2(P, V01[3], x01); x23 = fma2(P, V23[3], x23);
                o01[j] = x01; o23[j] = x23;
            }
        }
        __syncwarp();   // protect p_w before next iteration's overwrite
    }

    // ---- epilogue: merge 8 per-warp (m,l,O) by log-sum-exp, write partial ----
    if (rr == 0) { m_sm[w][adq] = m_run; l_sm[w][adq] = l_run; }
    __syncthreads();

    float sc[TQ_];
#pragma unroll
    for (int j = 0; j < TQ_; j++) {
        float M = m_sm[0][j];
#pragma unroll
        for (int w2 = 1; w2 < 8; w2++) M = fmaxf(M, m_sm[w2][j]);
        sc[j] = __expf(m_sm[w][j] - M);   // this warp's rescale to CTA max
    }
    {
        const size_t pbase = (size_t)bid * (TQ_ * D_);
#pragma unroll 1
        for (int j = 0; j < TQ_; j++) {
            __syncthreads();   // previous iteration's reads done
            const u64 S2 = pack2(sc[j], sc[j]);
            const float2 a01 = unpack2(mul2(o01[j], S2));
            const float2 a23 = unpack2(mul2(o23[j], S2));
            *(float4*)&red_sm[w][bd] = make_float4(a01.x, a01.y, a23.x, a23.y);
            __syncthreads();
            if (t < D_) {
                float acc = red_sm[0][t];
#pragma unroll
                for (int w2 = 1; w2 < 8; w2++) acc += red_sm[w2][t];
                g_po[pbase + j * D_ + t] = acc;
            }
        }
        if (t < TQ_) {   // thread t == query j
            float M = m_sm[0][t];
#pragma unroll
            for (int w2 = 1; w2 < 8; w2++) M = fmaxf(M, m_sm[w2][t]);
            float L = 0.0f;
#pragma unroll
            for (int w2 = 0; w2 < 8; w2++)
                L = fmaf(__expf(m_sm[w2][t] - M), l_sm[w2][t], L);
            g_pm[bid * TQ_ + t] = M;
            g_pl[bid * TQ_ + t] = L;
        }
    }
}

__global__ __launch_bounds__(256)
void combine_kernel(float* __restrict__ out)
{
    const int bh = blockIdx.x;          // 0..255
    const int t  = threadIdx.x;
    const int j  = t >> 5;              // query
    const int d4 = (t & 31) << 2;       // column base

    float m[NSPLIT_];
    float M = -INFINITY;
#pragma unroll
    for (int i = 0; i < NSPLIT_; i++) {
        m[i] = g_pm[(bh * NSPLIT_ + i) * TQ_ + j];
        M = fmaxf(M, m[i]);
    }
    float W = 0.0f;
    float ax = 0.f, ay = 0.f, az = 0.f, aw = 0.f;
#pragma unroll
    for (int i = 0; i < NSPLIT_; i++) {
        const float wgt = __expf(m[i] - M);
        W = fmaf(wgt, g_pl[(bh * NSPLIT_ + i) * TQ_ + j], W);
        const float4 oi = *(const float4*)&g_po[((size_t)(bh * NSPLIT_ + i) * TQ_ + j) * D_ + d4];
        ax = fmaf(wgt, oi.x, ax);
        ay = fmaf(wgt, oi.y, ay);
        az = fmaf(wgt, oi.z, az);
        aw = fmaf(wgt, oi.w, aw);
    }
    const float inv = 1.0f / W;
    float4 r = make_float4(ax * inv, ay * inv, az * inv, aw * inv);
    *(float4*)&out[(size_t)bh * (TQ_ * D_) + j * D_ + d4] = r;
}

// diagnostic: pads launch count so ncu (-s 5 -c 1, observed +2 offset)
// lands on attn_split_kernel (profiled slot = our 4th launch)
__global__ void nop_kernel() {}

extern "C" void kernel_launch(void* const* d_in, const int* in_sizes, int n_in,
                              void* d_out, int out_size)
{
    const float* q    = (const float*)d_in[0];
    const float* k    = (const float*)d_in[1];
    const float* v    = (const float*)d_in[2];
    const float* logt = (const float*)d_in[3];
    float* out = (float*)d_out;

    nop_kernel<<<1, 32>>>();
    nop_kernel<<<1, 32>>>();
    nop_kernel<<<1, 32>>>();
    attn_split_kernel<<<NPART_, 256>>>(q, k, v, logt);
    combine_kernel<<<B_ * H_, 256>>>(out);
}